// round 11
// baseline (speedup 1.0000x reference)
#include <cuda_runtime.h>

// NashCascadeNetwork: 8 layers x 524288 buckets, 8 spigots/bucket.
// Inputs (metadata order): H[NB] f32, S[NB,8,2] f32, theta[NB*8] f32, precip[1] f32
// Output (f32): [ H_new(NB) | s_q(NB*8) | network_outflow(1) ]
//
// One bucket per thread (R9 structure), 512-thread blocks:
// - 6x128b + 1x32b coalesced streaming loads per thread, front-batched
// - bucket outflow reduced in-register, b-1 coupling via shfl_up + smem carry
// - block-boundary bucket recomputed once per block by warp 0 (lanes 0-7)
// - fused, bit-deterministic last-layer network-outflow reduction

#define NB          4194304
#define NS          8
#define BPL         524288                   // buckets in last layer
#define NTHREADS    512
#define BPB         512                      // buckets per block (1 per thread)
#define NWARPS      (NTHREADS / 32)          // 16
#define NGRID       (NB / BPB)               // 8192
#define FIRST_LAST  ((NB - BPL) / BPB)       // 7168
#define NLASTBLK    (BPL / BPB)              // 1024
#define OUT_SQ_OFF  NB
#define OUT_SCALAR  (NB * (NS + 1))          // 37748736

__device__ double   g_partials[NLASTBLK];
__device__ unsigned g_count = 0;

// q = theta * sqrt(2*9.8*h) * 0.5*(tanh(h)+1) * area,  h = max(0, H - height)
// 0.5*(tanh(h)+1) == sigmoid(2h) == 1/(1+exp(-2h))  -> EX2 + RCP (err ~1e-7)
__device__ __forceinline__ float spigot_q(float Hb, float sh, float sa, float th) {
    float h = fmaxf(0.0f, Hb - sh);
    float e = __expf(-2.0f * h);
    float mod;
    asm("rcp.approx.f32 %0, %1;" : "=f"(mod) : "f"(1.0f + e));
    float s;
    asm("sqrt.approx.f32 %0, %1;" : "=f"(s) : "f"(19.6f * h));
    return th * s * mod * sa;
}

__global__ __launch_bounds__(NTHREADS)
void nash_main(const float* __restrict__ H,
               const float4* __restrict__ S4,     // [NB*4]
               const float4* __restrict__ T4,     // [NB*2]
               const float* __restrict__ precip,
               float* __restrict__ out)
{
    float*  Hn  = out;
    float4* SQ4 = (float4*)(out + OUT_SQ_OFF);

    const int tid  = threadIdx.x;
    const int lane = tid & 31;
    const int warp = tid >> 5;
    const int b    = blockIdx.x * BPB + tid;

    // ---- front-batched streaming loads: whole bucket in 6x128b + 1x32b ----
    const float  Hb = H[b];
    const float4 s0 = __ldcs(&S4[(size_t)b * 4 + 0]);
    const float4 s1 = __ldcs(&S4[(size_t)b * 4 + 1]);
    const float4 s2 = __ldcs(&S4[(size_t)b * 4 + 2]);
    const float4 s3 = __ldcs(&S4[(size_t)b * 4 + 3]);
    const float4 t0 = __ldcs(&T4[(size_t)b * 2 + 0]);
    const float4 t1 = __ldcs(&T4[(size_t)b * 2 + 1]);

    // ---- block-boundary bucket (b0-1): warp 0, lanes 0-7, one spigot each ----
    float pe = 0.0f;
    if (warp == 0) {
        if (blockIdx.x != 0 && lane < 8) {
            const int    bp = blockIdx.x * BPB - 1;
            const float  Hp = H[bp];
            const float2 sp = ((const float2*)S4)[(size_t)bp * 8 + lane];
            const float  tp = ((const float*)T4)[(size_t)bp * 8 + lane];
            pe = spigot_q(Hp, sp.x, sp.y, tp);
        }
        pe += __shfl_xor_sync(0xffffffffu, pe, 1);
        pe += __shfl_xor_sync(0xffffffffu, pe, 2);
        pe += __shfl_xor_sync(0xffffffffu, pe, 4);   // lane 0 = full sum
    }

    // ---- 8 spigots, all in-register ----
    const float q0 = spigot_q(Hb, s0.x, s0.y, t0.x);
    const float q1 = spigot_q(Hb, s0.z, s0.w, t0.y);
    const float q2 = spigot_q(Hb, s1.x, s1.y, t0.z);
    const float q3 = spigot_q(Hb, s1.z, s1.w, t0.w);
    const float q4 = spigot_q(Hb, s2.x, s2.y, t1.x);
    const float q5 = spigot_q(Hb, s2.z, s2.w, t1.y);
    const float q6 = spigot_q(Hb, s3.x, s3.y, t1.z);
    const float q7 = spigot_q(Hb, s3.z, s3.w, t1.w);

    __stcs(&SQ4[(size_t)b * 2 + 0], make_float4(q0, q1, q2, q3));
    __stcs(&SQ4[(size_t)b * 2 + 1], make_float4(q4, q5, q6, q7));

    const float ob = ((q0 + q1) + (q2 + q3)) + ((q4 + q5) + (q6 + q7));

    // ---- inflow[b] = outflow[b-1]: shfl_up + smem warp carries ----
    float inflow = __shfl_up_sync(0xffffffffu, ob, 1);
    __shared__ float s_carry[NWARPS];
    if (lane == 31) s_carry[warp] = ob;
    __syncthreads();
    if (lane == 0)
        inflow = (warp == 0)
               ? ((blockIdx.x == 0) ? __ldg(precip) : pe)
               : s_carry[warp - 1];
    __stcs(&Hn[b], Hb + inflow - ob);

    // ---- last-layer network-outflow reduction (last 12.5% of blocks) ----
    if (blockIdx.x >= FIRST_LAST) {
        double a = (double)ob;
        a += __shfl_xor_sync(0xffffffffu, a, 16);
        a += __shfl_xor_sync(0xffffffffu, a, 8);
        a += __shfl_xor_sync(0xffffffffu, a, 4);
        a += __shfl_xor_sync(0xffffffffu, a, 2);
        a += __shfl_xor_sync(0xffffffffu, a, 1);

        __shared__ double sd[NWARPS];
        __shared__ bool   s_last;
        if (tid == 0) s_last = false;
        if (lane == 0) sd[warp] = a;
        __syncthreads();
        if (tid == 0) {
            double bs = 0.0;
            #pragma unroll
            for (int i = 0; i < NWARPS; i++) bs += sd[i];
            g_partials[blockIdx.x - FIRST_LAST] = bs;
            __threadfence();
            unsigned t = atomicAdd(&g_count, 1u);
            if (t == NLASTBLK - 1) s_last = true;
        }
        __syncthreads();

        if (s_last) {
            // Last block alive: fixed-order reduction (bit-deterministic).
            __threadfence();
            double acc = 0.0;
            #pragma unroll 2
            for (int i = tid; i < NLASTBLK; i += NTHREADS)
                acc += g_partials[i];
            __shared__ double sm[NTHREADS];
            sm[tid] = acc;
            __syncthreads();
            #pragma unroll
            for (int s = NTHREADS / 2; s > 0; s >>= 1) {
                if (tid < s) sm[tid] += sm[tid + s];
                __syncthreads();
            }
            if (tid == 0) {
                out[OUT_SCALAR] = (float)sm[0];
                g_count = 0;                     // reset for graph replay
            }
        }
    }
}

extern "C" void kernel_launch(void* const* d_in, const int* in_sizes, int n_in,
                              void* d_out, int out_size) {
    const float*  H      = (const float*)d_in[0];
    const float4* S4     = (const float4*)d_in[1];
    const float4* T4     = (const float4*)d_in[2];
    const float*  precip = (const float*)d_in[3];

    nash_main<<<NGRID, NTHREADS>>>(H, S4, T4, precip, (float*)d_out);
}

// round 12
// speedup vs baseline: 1.0309x; 1.0309x over previous
#include <cuda_runtime.h>

// NashCascadeNetwork: 8 layers x 524288 buckets, 8 spigots/bucket.
// Inputs (metadata order): H[NB] f32, S[NB,8,2] f32, theta[NB*8] f32, precip[1] f32
// Output (f32): [ H_new(NB) | s_q(NB*8) | network_outflow(1) ]
//
// R9 structure (one bucket per thread, shfl_up carry + one cheap barrier),
// block size 128 (single-variable change vs the 90.0us best):
// - 6x128b + 1x32b coalesced streaming loads per thread, front-batched
// - bucket outflow reduced in-register, b-1 coupling via shfl_up + smem carry
// - block-boundary bucket recomputed once per block by warp 0 (lanes 0-7)
// - fused, bit-deterministic last-layer network-outflow reduction

#define NB          4194304
#define NS          8
#define BPL         524288                   // buckets in last layer
#define NTHREADS    128
#define BPB         128                      // buckets per block (1 per thread)
#define NWARPS      (NTHREADS / 32)          // 4
#define NGRID       (NB / BPB)               // 32768
#define FIRST_LAST  ((NB - BPL) / BPB)       // 28672
#define NLASTBLK    (BPL / BPB)              // 4096
#define OUT_SQ_OFF  NB
#define OUT_SCALAR  (NB * (NS + 1))          // 37748736

__device__ double   g_partials[NLASTBLK];
__device__ unsigned g_count = 0;

// q = theta * sqrt(2*9.8*h) * 0.5*(tanh(h)+1) * area,  h = max(0, H - height)
// 0.5*(tanh(h)+1) == sigmoid(2h) == 1/(1+exp(-2h))  -> EX2 + RCP (err ~1e-7)
__device__ __forceinline__ float spigot_q(float Hb, float sh, float sa, float th) {
    float h = fmaxf(0.0f, Hb - sh);
    float e = __expf(-2.0f * h);
    float mod;
    asm("rcp.approx.f32 %0, %1;" : "=f"(mod) : "f"(1.0f + e));
    float s;
    asm("sqrt.approx.f32 %0, %1;" : "=f"(s) : "f"(19.6f * h));
    return th * s * mod * sa;
}

__global__ __launch_bounds__(NTHREADS)
void nash_main(const float* __restrict__ H,
               const float4* __restrict__ S4,     // [NB*4]
               const float4* __restrict__ T4,     // [NB*2]
               const float* __restrict__ precip,
               float* __restrict__ out)
{
    float*  Hn  = out;
    float4* SQ4 = (float4*)(out + OUT_SQ_OFF);

    const int tid  = threadIdx.x;
    const int lane = tid & 31;
    const int warp = tid >> 5;
    const int b    = blockIdx.x * BPB + tid;

    // ---- front-batched streaming loads: whole bucket in 6x128b + 1x32b ----
    const float  Hb = H[b];
    const float4 s0 = __ldcs(&S4[(size_t)b * 4 + 0]);
    const float4 s1 = __ldcs(&S4[(size_t)b * 4 + 1]);
    const float4 s2 = __ldcs(&S4[(size_t)b * 4 + 2]);
    const float4 s3 = __ldcs(&S4[(size_t)b * 4 + 3]);
    const float4 t0 = __ldcs(&T4[(size_t)b * 2 + 0]);
    const float4 t1 = __ldcs(&T4[(size_t)b * 2 + 1]);

    // ---- block-boundary bucket (b0-1): warp 0, lanes 0-7, one spigot each ----
    float pe = 0.0f;
    if (warp == 0) {
        if (blockIdx.x != 0 && lane < 8) {
            const int    bp = blockIdx.x * BPB - 1;
            const float  Hp = H[bp];
            const float2 sp = ((const float2*)S4)[(size_t)bp * 8 + lane];
            const float  tp = ((const float*)T4)[(size_t)bp * 8 + lane];
            pe = spigot_q(Hp, sp.x, sp.y, tp);
        }
        pe += __shfl_xor_sync(0xffffffffu, pe, 1);
        pe += __shfl_xor_sync(0xffffffffu, pe, 2);
        pe += __shfl_xor_sync(0xffffffffu, pe, 4);   // lane 0 = full sum
    }

    // ---- 8 spigots, all in-register ----
    const float q0 = spigot_q(Hb, s0.x, s0.y, t0.x);
    const float q1 = spigot_q(Hb, s0.z, s0.w, t0.y);
    const float q2 = spigot_q(Hb, s1.x, s1.y, t0.z);
    const float q3 = spigot_q(Hb, s1.z, s1.w, t0.w);
    const float q4 = spigot_q(Hb, s2.x, s2.y, t1.x);
    const float q5 = spigot_q(Hb, s2.z, s2.w, t1.y);
    const float q6 = spigot_q(Hb, s3.x, s3.y, t1.z);
    const float q7 = spigot_q(Hb, s3.z, s3.w, t1.w);

    __stcs(&SQ4[(size_t)b * 2 + 0], make_float4(q0, q1, q2, q3));
    __stcs(&SQ4[(size_t)b * 2 + 1], make_float4(q4, q5, q6, q7));

    const float ob = ((q0 + q1) + (q2 + q3)) + ((q4 + q5) + (q6 + q7));

    // ---- inflow[b] = outflow[b-1]: shfl_up + smem warp carries ----
    float inflow = __shfl_up_sync(0xffffffffu, ob, 1);
    __shared__ float s_carry[NWARPS];
    if (lane == 31) s_carry[warp] = ob;
    __syncthreads();
    if (lane == 0)
        inflow = (warp == 0)
               ? ((blockIdx.x == 0) ? __ldg(precip) : pe)
               : s_carry[warp - 1];
    __stcs(&Hn[b], Hb + inflow - ob);

    // ---- last-layer network-outflow reduction (last 12.5% of blocks) ----
    if (blockIdx.x >= FIRST_LAST) {
        double a = (double)ob;
        a += __shfl_xor_sync(0xffffffffu, a, 16);
        a += __shfl_xor_sync(0xffffffffu, a, 8);
        a += __shfl_xor_sync(0xffffffffu, a, 4);
        a += __shfl_xor_sync(0xffffffffu, a, 2);
        a += __shfl_xor_sync(0xffffffffu, a, 1);

        __shared__ double sd[NWARPS];
        __shared__ bool   s_last;
        if (tid == 0) s_last = false;
        if (lane == 0) sd[warp] = a;
        __syncthreads();
        if (tid == 0) {
            double bs = ((sd[0] + sd[1]) + (sd[2] + sd[3]));
            g_partials[blockIdx.x - FIRST_LAST] = bs;
            __threadfence();
            unsigned t = atomicAdd(&g_count, 1u);
            if (t == NLASTBLK - 1) s_last = true;
        }
        __syncthreads();

        if (s_last) {
            // Last block alive: fixed-order reduction (bit-deterministic).
            __threadfence();
            double acc = 0.0;
            #pragma unroll 8
            for (int i = tid; i < NLASTBLK; i += NTHREADS)
                acc += g_partials[i];
            __shared__ double sm[NTHREADS];
            sm[tid] = acc;
            __syncthreads();
            #pragma unroll
            for (int s = NTHREADS / 2; s > 0; s >>= 1) {
                if (tid < s) sm[tid] += sm[tid + s];
                __syncthreads();
            }
            if (tid == 0) {
                out[OUT_SCALAR] = (float)sm[0];
                g_count = 0;                     // reset for graph replay
            }
        }
    }
}

extern "C" void kernel_launch(void* const* d_in, const int* in_sizes, int n_in,
                              void* d_out, int out_size) {
    const float*  H      = (const float*)d_in[0];
    const float4* S4     = (const float4*)d_in[1];
    const float4* T4     = (const float4*)d_in[2];
    const float*  precip = (const float*)d_in[3];

    nash_main<<<NGRID, NTHREADS>>>(H, S4, T4, precip, (float*)d_out);
}